// round 15
// baseline (speedup 1.0000x reference)
#include <cuda_runtime.h>

#define HW (768*768)

#define C3  (1.0f / 3.0f)
#define C81 (1.0f / 81.0f)

typedef unsigned long long ull;

// ---- packed f32x2 helpers (each lane = independent rn fp32 op) ----
__device__ __forceinline__ ull addx2(ull a, ull b) {
    ull r; asm("add.rn.f32x2 %0, %1, %2;" : "=l"(r) : "l"(a), "l"(b)); return r;
}
__device__ __forceinline__ ull mulx2(ull a, ull b) {
    ull r; asm("mul.rn.f32x2 %0, %1, %2;" : "=l"(r) : "l"(a), "l"(b)); return r;
}
// acc - old == fma(old, -1, acc) (single rounding per lane)
__device__ __forceinline__ ull subx2(ull acc, ull old) {
    ull r;
    asm("fma.rn.f32x2 %0, %1, %2, %3;" : "=l"(r)
        : "l"(old), "l"(0xBF800000BF800000ULL), "l"(acc));
    return r;
}
__device__ __forceinline__ float flo(ull v) { return __uint_as_float((unsigned)v); }
__device__ __forceinline__ float fhi(ull v) { return __uint_as_float((unsigned)(v >> 32)); }

// column-only swizzle (bijective; conflict-free per 8-lane phase; pitch 608B)
__device__ __forceinline__ unsigned csw(int c) {
    return (unsigned)((c * 8) ^ (c & 16));
}

// ---- smem layout (bytes) ----
#define PS_OFF 0            // 56 x 76 float2 (sx,sy), pitch 608 : 34048
#define M_OFF  34048        // 58 x 80 float (channel mean)      : 18560
#define NQ_OFF 52608
#define Q_OFF  52612
#define QCAP   512
#define SMEM_BYTES (52612 + QCAP * 2)

// exact-order recompute (reduce_window flat row-major, strict rn everywhere)
__device__ __noinline__ void exact_pixel(const char* Ps, float* ob,
                                         int row0, int col0, int i, int j) {
    float axx = 0.f, ayy = 0.f, axy = 0.f;
    #pragma unroll 1
    for (int r = 0; r < 9; r++) {
        const char* pr = Ps + (i + r) * 608;
        #pragma unroll
        for (int c = 0; c < 9; c++) {
            float2 s = *(const float2*)(pr + csw(j + c));
            axx = __fadd_rn(axx, __fmul_rn(s.x, s.x));
            ayy = __fadd_rn(ayy, __fmul_rn(s.y, s.y));
            axy = __fadd_rn(axy, __fmul_rn(s.x, s.y));
        }
    }
    float xx = __fmul_rn(axx, C81);
    float yy = __fmul_rn(ayy, C81);
    float xy = __fmul_rn(axy, C81);
    float tr = __fadd_rn(xx, yy);
    float bq = -tr;
    float cq = __fsub_rn(__fmul_rn(xx, yy), __fmul_rn(xy, xy));
    float disc = __fsub_rn(__fmul_rn(bq, bq), __fmul_rn(4.f, cq));
    disc = fmaxf(disc, 0.f);
    float deta = __fsqrt_rn(disc);
    float l1 = __fmul_rn(__fadd_rn(tr, deta), 0.5f);
    float yd = __fsub_rn(xx, l1);
    float s2 = __fadd_rn(__fadd_rn(__fmul_rn(xy, xy), __fmul_rn(yd, yd)), 1e-8f);
    float l  = __fadd_rn(__fsqrt_rn(s2), 1e-8f);
    float ex = __fdiv_rn(xy, l);
    float ey = __fdiv_rn(yd, l);
    size_t o = (size_t)(row0 + i) * 768 + (col0 + j);
    ob[o] = ex; ob[o + HW] = ey; ob[o + 2 * HW] = ex;
}

// one (sx,sy) row: products on the fly; horizontal 9-sums via shared core
// C = p1..p8 (parallel form, short chains); vertical accumulate into rows [LO..HI].
template<int LO, int HI>
__device__ __forceinline__ void row3(
    const char* __restrict__ Ps, unsigned (&ap2)[6],
    ull (&a2)[3][4], float (&axy)[3][4])
{
    ulonglong2 A = *(const ulonglong2*)(Ps + ap2[0]);  ap2[0] += 608;
    ulonglong2 B = *(const ulonglong2*)(Ps + ap2[1]);  ap2[1] += 608;
    ull p0 = mulx2(A.x, A.x), p1 = mulx2(A.y, A.y);
    ull p2 = mulx2(B.x, B.x), p3 = mulx2(B.y, B.y);
    float s0 = __fmul_rn(flo(A.x), fhi(A.x));
    float s1 = __fmul_rn(flo(A.y), fhi(A.y));
    float s2v = __fmul_rn(flo(B.x), fhi(B.x));
    float s3 = __fmul_rn(flo(B.y), fhi(B.y));
    ull u12 = addx2(p1, p2);
    float z12 = __fadd_rn(s1, s2v);

    A = *(const ulonglong2*)(Ps + ap2[2]);  ap2[2] += 608;
    B = *(const ulonglong2*)(Ps + ap2[3]);  ap2[3] += 608;
    ull p4 = mulx2(A.x, A.x), p5 = mulx2(A.y, A.y);
    ull p6 = mulx2(B.x, B.x), p7 = mulx2(B.y, B.y);
    float s4 = __fmul_rn(flo(A.x), fhi(A.x));
    float s5 = __fmul_rn(flo(A.y), fhi(A.y));
    float s6 = __fmul_rn(flo(B.x), fhi(B.x));
    float s7 = __fmul_rn(flo(B.y), fhi(B.y));
    ull u34 = addx2(p3, p4), u56 = addx2(p5, p6);
    float z34 = __fadd_rn(s3, s4), z56 = __fadd_rn(s5, s6);

    A = *(const ulonglong2*)(Ps + ap2[4]);  ap2[4] += 608;
    B = *(const ulonglong2*)(Ps + ap2[5]);  ap2[5] += 608;
    ull p8 = mulx2(A.x, A.x), p9 = mulx2(A.y, A.y);
    ull p10 = mulx2(B.x, B.x), p11 = mulx2(B.y, B.y);
    float s8 = __fmul_rn(flo(A.x), fhi(A.x));
    float s9 = __fmul_rn(flo(A.y), fhi(A.y));
    float s10 = __fmul_rn(flo(B.x), fhi(B.x));
    float s11 = __fmul_rn(flo(B.y), fhi(B.y));

    ull u78 = addx2(p7, p8);
    ull Csum = addx2(addx2(u12, u34), addx2(u56, u78));
    ull h0 = addx2(Csum, p0);
    ull h1 = addx2(Csum, p9);
    ull hA = subx2(Csum, p1);
    ull pq = addx2(p9, p10);
    ull h2 = addx2(hA, pq);
    ull hB = subx2(hA, p2);
    ull h3 = addx2(hB, addx2(pq, p11));

    float z78 = __fadd_rn(s7, s8);
    float Zs = __fadd_rn(__fadd_rn(z12, z34), __fadd_rn(z56, z78));
    float w0 = __fadd_rn(Zs, s0);
    float w1 = __fadd_rn(Zs, s9);
    float zA = __fsub_rn(Zs, s1);
    float zq = __fadd_rn(s9, s10);
    float w2 = __fadd_rn(zA, zq);
    float zB = __fsub_rn(zA, s2v);
    float w3 = __fadd_rn(zB, __fadd_rn(zq, s11));

    #pragma unroll
    for (int oi = LO; oi <= HI; oi++) {
        a2[oi][0] = addx2(a2[oi][0], h0);
        a2[oi][1] = addx2(a2[oi][1], h1);
        a2[oi][2] = addx2(a2[oi][2], h2);
        a2[oi][3] = addx2(a2[oi][3], h3);
        axy[oi][0] = __fadd_rn(axy[oi][0], w0);
        axy[oi][1] = __fadd_rn(axy[oi][1], w1);
        axy[oi][2] = __fadd_rn(axy[oi][2], w2);
        axy[oi][3] = __fadd_rn(axy[oi][3], w3);
    }
}

__global__ void __launch_bounds__(256, 3) k_fused(const float* __restrict__ x,
                                                  float* __restrict__ out) {
    extern __shared__ char smem[];
    char*  Ps  = smem + PS_OFF;
    float* M   = (float*)(smem + M_OFF);
    int*   nflag = (int*)(smem + NQ_OFF);
    unsigned short* qbuf = (unsigned short*)(smem + Q_OFF);

    const int col0 = blockIdx.x * 64;
    const int row0 = blockIdx.y * 48;
    const int b    = blockIdx.z;
    const int t    = threadIdx.x;
    const float* xb = x + (size_t)b * 3 * HW;
    float* ob = out + (size_t)b * 3 * HW;

    if (t == 0) *nflag = 0;

    // ---- Phase A: M[58][80] = channel mean; M[0][0] <-> src (row0-5, col0-8).
    for (int s = t; s < 58 * 20; s += 256) {
        int mr = s / 20, k = s - mr * 20;
        int gr = row0 - 5 + mr;
        int gc = col0 - 8 + 4 * k;
        float4 v = make_float4(0.f, 0.f, 0.f, 0.f);
        if ((unsigned)gr < 768u && (unsigned)gc <= 764u) {
            size_t off = (size_t)gr * 768 + gc;
            float4 a  = *(const float4*)(xb + off);
            float4 c1 = *(const float4*)(xb + HW + off);
            float4 c2 = *(const float4*)(xb + 2 * HW + off);
            v.x = __fmul_rn(__fadd_rn(__fadd_rn(a.x, c1.x), c2.x), C3);
            v.y = __fmul_rn(__fadd_rn(__fadd_rn(a.y, c1.y), c2.y), C3);
            v.z = __fmul_rn(__fadd_rn(__fadd_rn(a.z, c1.z), c2.z), C3);
            v.w = __fmul_rn(__fadd_rn(__fadd_rn(a.w, c1.w), c2.w), C3);
        }
        *(float4*)&M[mr * 80 + 4 * k] = v;
    }
    __syncthreads();

    // ---- Phase B: scalar Sobel (R10-proven exact reference op order) -> Ps.
    //      Ps(pr,pc) <-> src (row0-4+pr, col0-4+pc); OOB -> 0.
    for (int s = t; s < 56 * 72; s += 256) {
        int pr = s / 72, pc = s - pr * 72;
        int sr = row0 - 4 + pr, sc = col0 - 4 + pc;
        float sxv = 0.f, syv = 0.f;
        if ((unsigned)sr < 768u && (unsigned)sc < 768u) {
            int mr = pr + 1, mc = pc + 4;
            const float* r0p = &M[(mr - 1) * 80 + mc];
            const float* r1p = &M[ mr      * 80 + mc];
            const float* r2p = &M[(mr + 1) * 80 + mc];
            float m00 = r0p[-1], m01 = r0p[0], m02 = r0p[1];
            float m10 = r1p[-1],               m12 = r1p[1];
            float m20 = r2p[-1], m21 = r2p[0], m22 = r2p[1];

            float rlx_u = __fsub_rn(m02, m00);
            float rlx_c = __fsub_rn(m12, m10);
            float rlx_d = __fsub_rn(m22, m20);
            float tx3 = __fadd_rn(__fadd_rn(rlx_u, rlx_c), rlx_d);
            sxv = __fadd_rn(rlx_c, __fmul_rn(__fmul_rn(tx3, C3), 3.f));

            float btx_l = __fsub_rn(m20, m00);
            float btx_c = __fsub_rn(m21, m01);
            float btx_r = __fsub_rn(m22, m02);
            float ty3 = __fadd_rn(__fadd_rn(btx_l, btx_c), btx_r);
            syv = __fadd_rn(btx_c, __fmul_rn(__fmul_rn(ty3, C3), 3.f));
        }
        *(float2*)(Ps + pr * 608 + csw(pc)) = make_float2(sxv, syv);
    }
    __syncthreads();

    // ---- Phase C: 3 rows x 4 cols per thread; 11-row sweep, carried addresses.
    const int uj = t & 15, ui = t >> 4;
    const int oc   = uj * 4;
    const int orow = ui * 3;

    ull a2[3][4];
    float axy[3][4];
    #pragma unroll
    for (int oi = 0; oi < 3; oi++)
        #pragma unroll
        for (int cc = 0; cc < 4; cc++) { a2[oi][cc] = 0ull; axy[oi][cc] = 0.f; }

    unsigned ap2[6];
    #pragma unroll
    for (int k = 0; k < 6; k++) ap2[k] = (unsigned)(orow * 608) + csw(oc + 2 * k);

    row3<0, 0>(Ps, ap2, a2, axy);
    row3<0, 1>(Ps, ap2, a2, axy);
    row3<0, 2>(Ps, ap2, a2, axy);
    row3<0, 2>(Ps, ap2, a2, axy);
    row3<0, 2>(Ps, ap2, a2, axy);
    row3<0, 2>(Ps, ap2, a2, axy);
    row3<0, 2>(Ps, ap2, a2, axy);
    row3<0, 2>(Ps, ap2, a2, axy);
    row3<0, 2>(Ps, ap2, a2, axy);
    row3<1, 2>(Ps, ap2, a2, axy);
    row3<2, 2>(Ps, ap2, a2, axy);

    // ---- eigen math (strict rn) + flag (widened band) + store
    #pragma unroll
    for (int oi = 0; oi < 3; oi++) {
        float ex4[4], ey4[4];
        #pragma unroll
        for (int cc = 0; cc < 4; cc++) {
            ull v = a2[oi][cc];
            float xx = __fmul_rn(flo(v), C81);
            float yy = __fmul_rn(fhi(v), C81);
            float xy = __fmul_rn(axy[oi][cc], C81);
            float tr = __fadd_rn(xx, yy);
            float cq = __fsub_rn(__fmul_rn(xx, yy), __fmul_rn(xy, xy));
            float disc = __fsub_rn(__fmul_rn(tr, tr), __fmul_rn(4.f, cq));
            disc = fmaxf(disc, 0.f);
            float deta = __fsqrt_rn(disc);
            float l1 = __fmul_rn(__fadd_rn(tr, deta), 0.5f);
            float yd = __fsub_rn(xx, l1);
            float s2r = __fadd_rn(__fmul_rn(xy, xy), __fmul_rn(yd, yd));

            if (s2r < 2.5e-5f * tr * tr) {   // near-degenerate: exact recompute
                int qi = atomicAdd(nflag, 1);
                int li = orow + oi, lj = oc + cc;
                if (qi < QCAP) qbuf[qi] = (unsigned short)((li << 6) | lj);
                else exact_pixel(Ps, ob, row0, col0, li, lj);
            }
            float l  = __fadd_rn(__fsqrt_rn(__fadd_rn(s2r, 1e-8f)), 1e-8f);
            ex4[cc] = __fdiv_rn(xy, l);
            ey4[cc] = __fdiv_rn(yd, l);
        }
        size_t o = (size_t)(row0 + orow + oi) * 768 + (col0 + oc);
        *(float4*)&ob[o]          = make_float4(ex4[0], ex4[1], ex4[2], ex4[3]);
        *(float4*)&ob[o + HW]     = make_float4(ey4[0], ey4[1], ey4[2], ey4[3]);
        *(float4*)&ob[o + 2*HW]   = make_float4(ex4[0], ex4[1], ex4[2], ex4[3]);
    }
    __syncthreads();

    // ---- Phase D: exact overwrite of flagged pixels (rare; single writer each).
    int nf = *nflag;
    if (nf > QCAP) nf = QCAP;
    for (int q = t; q < nf; q += 256) {
        int e = qbuf[q];
        exact_pixel(Ps, ob, row0, col0, e >> 6, e & 63);
    }
}

extern "C" void kernel_launch(void* const* d_in, const int* in_sizes, int n_in,
                              void* d_out, int out_size) {
    const float* x = (const float*)d_in[0];
    float* out = (float*)d_out;

    cudaFuncSetAttribute(k_fused, cudaFuncAttributeMaxDynamicSharedMemorySize, SMEM_BYTES);
    dim3 grid(768 / 64, 768 / 48, 32);   // (12, 16, 32)
    k_fused<<<grid, 256, SMEM_BYTES>>>(x, out);
}

// round 16
// speedup vs baseline: 1.0783x; 1.0783x over previous
#include <cuda_runtime.h>

#define HW (768*768)

#define C3  (1.0f / 3.0f)
#define C81 (1.0f / 81.0f)

typedef unsigned long long ull;

// ---- packed f32x2 helpers (each lane = independent rn fp32 op) ----
__device__ __forceinline__ ull addx2(ull a, ull b) {
    ull r; asm("add.rn.f32x2 %0, %1, %2;" : "=l"(r) : "l"(a), "l"(b)); return r;
}
__device__ __forceinline__ ull mulx2(ull a, ull b) {
    ull r; asm("mul.rn.f32x2 %0, %1, %2;" : "=l"(r) : "l"(a), "l"(b)); return r;
}
// acc - old == fma(old, -1, acc) (single rounding per lane)
__device__ __forceinline__ ull subx2(ull acc, ull old) {
    ull r;
    asm("fma.rn.f32x2 %0, %1, %2, %3;" : "=l"(r)
        : "l"(old), "l"(0xBF800000BF800000ULL), "l"(acc));
    return r;
}
__device__ __forceinline__ float flo(ull v) { return __uint_as_float((unsigned)v); }
__device__ __forceinline__ float fhi(ull v) { return __uint_as_float((unsigned)(v >> 32)); }

// fast-path approx ops (MUFU pipe) — exonerated by R13/R15 bisection
__device__ __forceinline__ float sqapx(float x) {
    float r; asm("sqrt.approx.f32 %0, %1;" : "=f"(r) : "f"(x)); return r;
}
__device__ __forceinline__ float rcpapx(float x) {
    float r; asm("rcp.approx.f32 %0, %1;" : "=f"(r) : "f"(x)); return r;
}

// column-only swizzle (bijective; conflict-free per 8-lane phase; pitch 608B)
__device__ __forceinline__ unsigned csw(int c) {
    return (unsigned)((c * 8) ^ (c & 16));
}

// ---- smem layout (bytes) ----
#define PS_OFF 0            // 56 x 76 float2 (sx,sy), pitch 608 : 34048
#define M_OFF  34048        // 58 x 80 float (channel mean)      : 18560
#define NQ_OFF 52608
#define Q_OFF  52612
#define QCAP   512
#define SMEM_BYTES (52612 + QCAP * 2)

// exact-order recompute (reduce_window flat row-major, strict rn everywhere)
__device__ __noinline__ void exact_pixel(const char* Ps, float* ob,
                                         int row0, int col0, int i, int j) {
    float axx = 0.f, ayy = 0.f, axy = 0.f;
    #pragma unroll 1
    for (int r = 0; r < 9; r++) {
        const char* pr = Ps + (i + r) * 608;
        #pragma unroll
        for (int c = 0; c < 9; c++) {
            float2 s = *(const float2*)(pr + csw(j + c));
            axx = __fadd_rn(axx, __fmul_rn(s.x, s.x));
            ayy = __fadd_rn(ayy, __fmul_rn(s.y, s.y));
            axy = __fadd_rn(axy, __fmul_rn(s.x, s.y));
        }
    }
    float xx = __fmul_rn(axx, C81);
    float yy = __fmul_rn(ayy, C81);
    float xy = __fmul_rn(axy, C81);
    float tr = __fadd_rn(xx, yy);
    float bq = -tr;
    float cq = __fsub_rn(__fmul_rn(xx, yy), __fmul_rn(xy, xy));
    float disc = __fsub_rn(__fmul_rn(bq, bq), __fmul_rn(4.f, cq));
    disc = fmaxf(disc, 0.f);
    float deta = __fsqrt_rn(disc);
    float l1 = __fmul_rn(__fadd_rn(tr, deta), 0.5f);
    float yd = __fsub_rn(xx, l1);
    float s2 = __fadd_rn(__fadd_rn(__fmul_rn(xy, xy), __fmul_rn(yd, yd)), 1e-8f);
    float l  = __fadd_rn(__fsqrt_rn(s2), 1e-8f);
    float ex = __fdiv_rn(xy, l);
    float ey = __fdiv_rn(yd, l);
    size_t o = (size_t)(row0 + i) * 768 + (col0 + j);
    ob[o] = ex; ob[o + HW] = ey; ob[o + 2 * HW] = ex;
}

// one (sx,sy) row: products on the fly; horizontal 9-sums via shared core
// C = p1..p8 (parallel form, short chains); vertical accumulate into rows [LO..HI].
template<int LO, int HI>
__device__ __forceinline__ void row3(
    const char* __restrict__ Ps, unsigned (&ap2)[6],
    ull (&a2)[3][4], float (&axy)[3][4])
{
    ulonglong2 A = *(const ulonglong2*)(Ps + ap2[0]);  ap2[0] += 608;
    ulonglong2 B = *(const ulonglong2*)(Ps + ap2[1]);  ap2[1] += 608;
    ull p0 = mulx2(A.x, A.x), p1 = mulx2(A.y, A.y);
    ull p2 = mulx2(B.x, B.x), p3 = mulx2(B.y, B.y);
    float s0 = __fmul_rn(flo(A.x), fhi(A.x));
    float s1 = __fmul_rn(flo(A.y), fhi(A.y));
    float s2v = __fmul_rn(flo(B.x), fhi(B.x));
    float s3 = __fmul_rn(flo(B.y), fhi(B.y));
    ull u12 = addx2(p1, p2);
    float z12 = __fadd_rn(s1, s2v);

    A = *(const ulonglong2*)(Ps + ap2[2]);  ap2[2] += 608;
    B = *(const ulonglong2*)(Ps + ap2[3]);  ap2[3] += 608;
    ull p4 = mulx2(A.x, A.x), p5 = mulx2(A.y, A.y);
    ull p6 = mulx2(B.x, B.x), p7 = mulx2(B.y, B.y);
    float s4 = __fmul_rn(flo(A.x), fhi(A.x));
    float s5 = __fmul_rn(flo(A.y), fhi(A.y));
    float s6 = __fmul_rn(flo(B.x), fhi(B.x));
    float s7 = __fmul_rn(flo(B.y), fhi(B.y));
    ull u34 = addx2(p3, p4), u56 = addx2(p5, p6);
    float z34 = __fadd_rn(s3, s4), z56 = __fadd_rn(s5, s6);

    A = *(const ulonglong2*)(Ps + ap2[4]);  ap2[4] += 608;
    B = *(const ulonglong2*)(Ps + ap2[5]);  ap2[5] += 608;
    ull p8 = mulx2(A.x, A.x), p9 = mulx2(A.y, A.y);
    ull p10 = mulx2(B.x, B.x), p11 = mulx2(B.y, B.y);
    float s8 = __fmul_rn(flo(A.x), fhi(A.x));
    float s9 = __fmul_rn(flo(A.y), fhi(A.y));
    float s10 = __fmul_rn(flo(B.x), fhi(B.x));
    float s11 = __fmul_rn(flo(B.y), fhi(B.y));

    ull u78 = addx2(p7, p8);
    ull Csum = addx2(addx2(u12, u34), addx2(u56, u78));
    ull h0 = addx2(Csum, p0);
    ull h1 = addx2(Csum, p9);
    ull hA = subx2(Csum, p1);
    ull pq = addx2(p9, p10);
    ull h2 = addx2(hA, pq);
    ull hB = subx2(hA, p2);
    ull h3 = addx2(hB, addx2(pq, p11));

    float z78 = __fadd_rn(s7, s8);
    float Zs = __fadd_rn(__fadd_rn(z12, z34), __fadd_rn(z56, z78));
    float w0 = __fadd_rn(Zs, s0);
    float w1 = __fadd_rn(Zs, s9);
    float zA = __fsub_rn(Zs, s1);
    float zq = __fadd_rn(s9, s10);
    float w2 = __fadd_rn(zA, zq);
    float zB = __fsub_rn(zA, s2v);
    float w3 = __fadd_rn(zB, __fadd_rn(zq, s11));

    #pragma unroll
    for (int oi = LO; oi <= HI; oi++) {
        a2[oi][0] = addx2(a2[oi][0], h0);
        a2[oi][1] = addx2(a2[oi][1], h1);
        a2[oi][2] = addx2(a2[oi][2], h2);
        a2[oi][3] = addx2(a2[oi][3], h3);
        axy[oi][0] = __fadd_rn(axy[oi][0], w0);
        axy[oi][1] = __fadd_rn(axy[oi][1], w1);
        axy[oi][2] = __fadd_rn(axy[oi][2], w2);
        axy[oi][3] = __fadd_rn(axy[oi][3], w3);
    }
}

__global__ void __launch_bounds__(256, 3) k_fused(const float* __restrict__ x,
                                                  float* __restrict__ out) {
    extern __shared__ char smem[];
    char*  Ps  = smem + PS_OFF;
    float* M   = (float*)(smem + M_OFF);
    int*   nflag = (int*)(smem + NQ_OFF);
    unsigned short* qbuf = (unsigned short*)(smem + Q_OFF);

    const int col0 = blockIdx.x * 64;
    const int row0 = blockIdx.y * 48;
    const int b    = blockIdx.z;
    const int t    = threadIdx.x;
    const float* xb = x + (size_t)b * 3 * HW;
    float* ob = out + (size_t)b * 3 * HW;

    if (t == 0) *nflag = 0;

    // ---- Phase A: M[58][80] = channel mean; M[0][0] <-> src (row0-5, col0-8).
    for (int s = t; s < 58 * 20; s += 256) {
        int mr = s / 20, k = s - mr * 20;
        int gr = row0 - 5 + mr;
        int gc = col0 - 8 + 4 * k;
        float4 v = make_float4(0.f, 0.f, 0.f, 0.f);
        if ((unsigned)gr < 768u && (unsigned)gc <= 764u) {
            size_t off = (size_t)gr * 768 + gc;
            float4 a  = *(const float4*)(xb + off);
            float4 c1 = *(const float4*)(xb + HW + off);
            float4 c2 = *(const float4*)(xb + 2 * HW + off);
            v.x = __fmul_rn(__fadd_rn(__fadd_rn(a.x, c1.x), c2.x), C3);
            v.y = __fmul_rn(__fadd_rn(__fadd_rn(a.y, c1.y), c2.y), C3);
            v.z = __fmul_rn(__fadd_rn(__fadd_rn(a.z, c1.z), c2.z), C3);
            v.w = __fmul_rn(__fadd_rn(__fadd_rn(a.w, c1.w), c2.w), C3);
        }
        *(float4*)&M[mr * 80 + 4 * k] = v;
    }
    __syncthreads();

    // ---- Phase B: scalar Sobel (R10-proven exact reference op order) -> Ps.
    //      Ps(pr,pc) <-> src (row0-4+pr, col0-4+pc); OOB -> 0.
    for (int s = t; s < 56 * 72; s += 256) {
        int pr = s / 72, pc = s - pr * 72;
        int sr = row0 - 4 + pr, sc = col0 - 4 + pc;
        float sxv = 0.f, syv = 0.f;
        if ((unsigned)sr < 768u && (unsigned)sc < 768u) {
            int mr = pr + 1, mc = pc + 4;
            const float* r0p = &M[(mr - 1) * 80 + mc];
            const float* r1p = &M[ mr      * 80 + mc];
            const float* r2p = &M[(mr + 1) * 80 + mc];
            float m00 = r0p[-1], m01 = r0p[0], m02 = r0p[1];
            float m10 = r1p[-1],               m12 = r1p[1];
            float m20 = r2p[-1], m21 = r2p[0], m22 = r2p[1];

            float rlx_u = __fsub_rn(m02, m00);
            float rlx_c = __fsub_rn(m12, m10);
            float rlx_d = __fsub_rn(m22, m20);
            float tx3 = __fadd_rn(__fadd_rn(rlx_u, rlx_c), rlx_d);
            sxv = __fadd_rn(rlx_c, __fmul_rn(__fmul_rn(tx3, C3), 3.f));

            float btx_l = __fsub_rn(m20, m00);
            float btx_c = __fsub_rn(m21, m01);
            float btx_r = __fsub_rn(m22, m02);
            float ty3 = __fadd_rn(__fadd_rn(btx_l, btx_c), btx_r);
            syv = __fadd_rn(btx_c, __fmul_rn(__fmul_rn(ty3, C3), 3.f));
        }
        *(float2*)(Ps + pr * 608 + csw(pc)) = make_float2(sxv, syv);
    }
    __syncthreads();

    // ---- Phase C: 3 rows x 4 cols per thread; 11-row sweep, carried addresses.
    const int uj = t & 15, ui = t >> 4;
    const int oc   = uj * 4;
    const int orow = ui * 3;

    ull a2[3][4];
    float axy[3][4];
    #pragma unroll
    for (int oi = 0; oi < 3; oi++)
        #pragma unroll
        for (int cc = 0; cc < 4; cc++) { a2[oi][cc] = 0ull; axy[oi][cc] = 0.f; }

    unsigned ap2[6];
    #pragma unroll
    for (int k = 0; k < 6; k++) ap2[k] = (unsigned)(orow * 608) + csw(oc + 2 * k);

    row3<0, 0>(Ps, ap2, a2, axy);
    row3<0, 1>(Ps, ap2, a2, axy);
    row3<0, 2>(Ps, ap2, a2, axy);
    row3<0, 2>(Ps, ap2, a2, axy);
    row3<0, 2>(Ps, ap2, a2, axy);
    row3<0, 2>(Ps, ap2, a2, axy);
    row3<0, 2>(Ps, ap2, a2, axy);
    row3<0, 2>(Ps, ap2, a2, axy);
    row3<0, 2>(Ps, ap2, a2, axy);
    row3<1, 2>(Ps, ap2, a2, axy);
    row3<2, 2>(Ps, ap2, a2, axy);

    // ---- eigen math (approx on fast path; wide band protects boundary) + store
    #pragma unroll
    for (int oi = 0; oi < 3; oi++) {
        float ex4[4], ey4[4];
        #pragma unroll
        for (int cc = 0; cc < 4; cc++) {
            ull v = a2[oi][cc];
            float xx = flo(v) * C81;
            float yy = fhi(v) * C81;
            float xy = axy[oi][cc] * C81;
            float tr = xx + yy;
            float cq = xx * yy - xy * xy;
            float disc = tr * tr - 4.f * cq;
            disc = fmaxf(disc, 0.f);
            float deta = sqapx(disc);
            float l1 = (tr + deta) * 0.5f;
            float yd = xx - l1;
            float s2r = xy * xy + yd * yd;

            if (s2r < 2.5e-5f * tr * tr) {   // near-degenerate: exact recompute
                int qi = atomicAdd(nflag, 1);
                int li = orow + oi, lj = oc + cc;
                if (qi < QCAP) qbuf[qi] = (unsigned short)((li << 6) | lj);
                else exact_pixel(Ps, ob, row0, col0, li, lj);
            }
            float l = sqapx(s2r + 1e-8f) + 1e-8f;
            float inv = rcpapx(l);
            ex4[cc] = xy * inv;
            ey4[cc] = yd * inv;
        }
        size_t o = (size_t)(row0 + orow + oi) * 768 + (col0 + oc);
        *(float4*)&ob[o]          = make_float4(ex4[0], ex4[1], ex4[2], ex4[3]);
        *(float4*)&ob[o + HW]     = make_float4(ey4[0], ey4[1], ey4[2], ey4[3]);
        *(float4*)&ob[o + 2*HW]   = make_float4(ex4[0], ex4[1], ex4[2], ex4[3]);
    }
    __syncthreads();

    // ---- Phase D: exact overwrite of flagged pixels (rare; single writer each).
    int nf = *nflag;
    if (nf > QCAP) nf = QCAP;
    for (int q = t; q < nf; q += 256) {
        int e = qbuf[q];
        exact_pixel(Ps, ob, row0, col0, e >> 6, e & 63);
    }
}

extern "C" void kernel_launch(void* const* d_in, const int* in_sizes, int n_in,
                              void* d_out, int out_size) {
    const float* x = (const float*)d_in[0];
    float* out = (float*)d_out;

    cudaFuncSetAttribute(k_fused, cudaFuncAttributeMaxDynamicSharedMemorySize, SMEM_BYTES);
    dim3 grid(768 / 64, 768 / 48, 32);   // (12, 16, 32)
    k_fused<<<grid, 256, SMEM_BYTES>>>(x, out);
}